// round 7
// baseline (speedup 1.0000x reference)
#include <cuda_runtime.h>

#define NB 2
#define N1 4096
#define N2 16384
#define CF 64
#define KNN 8

// Scratch (static __device__ arrays per allocation rules)
__device__ float4 g_pts[NB * N1];            // original order: x,y,z,(unused)
__device__ float4 g_spts[NB * N1];           // x-sorted points
__device__ float  g_sx[NB * N1];             // x-sorted x values (search/edge)
__device__ int    g_sidx[NB * N1];           // sorted pos -> original index
__device__ float  g_gtab[NB * N1 * CF];      // W1_feat@feat + W1_xyz@xyz1 + b1
__device__ int    g_idx[NB * N2 * KNN];      // knn indices (original index space)

// ---------------------------------------------------------------------------
// Kernel 1: pack xyz1 into float4
// ---------------------------------------------------------------------------
__global__ void pack_kernel(const float* __restrict__ xyz1) {
    int i = blockIdx.x * blockDim.x + threadIdx.x;
    if (i >= NB * N1) return;
    int b = i / N1, j = i - b * N1;
    const float* p = xyz1 + (size_t)b * 3 * N1;
    g_pts[i] = make_float4(p[j], p[N1 + j], p[2 * N1 + j], 0.f);
}

// ---------------------------------------------------------------------------
// Kernel 1b: bitonic sort targets by x (one block per batch, 1024 threads).
// Produces g_spts / g_sx / g_sidx in ascending-x order.
// ---------------------------------------------------------------------------
__global__ void __launch_bounds__(1024) sort_kernel() {
    __shared__ float sk[N1];
    __shared__ int   si[N1];
    int b = blockIdx.x;
    int t = threadIdx.x;

    for (int i = t; i < N1; i += 1024) { sk[i] = g_pts[b * N1 + i].x; si[i] = i; }
    __syncthreads();

    for (int k = 2; k <= N1; k <<= 1) {
        for (int j = k >> 1; j > 0; j >>= 1) {
            for (int n = t; n < N1 / 2; n += 1024) {
                int i  = 2 * n - (n & (j - 1));
                int p2 = i + j;
                bool up = ((i & k) == 0);
                float a = sk[i], c = sk[p2];
                if ((a > c) == up) {
                    sk[i] = c; sk[p2] = a;
                    int ti = si[i]; si[i] = si[p2]; si[p2] = ti;
                }
            }
            __syncthreads();
        }
    }

    for (int i = t; i < N1; i += 1024) {
        int src = si[i];
        g_spts[b * N1 + i] = g_pts[b * N1 + src];
        g_sx[b * N1 + i]   = sk[i];
        g_sidx[b * N1 + i] = src;
    }
}

// ---------------------------------------------------------------------------
// Kernel 2: per-target transform  g[b][j][o] = sum_c W1[o][c]*in[c] + b1[o]
// ---------------------------------------------------------------------------
__global__ void __launch_bounds__(256) gmat_kernel(const float* __restrict__ feat1,
                                                   const float* __restrict__ xyz1,
                                                   const float* __restrict__ W1,
                                                   const float* __restrict__ b1) {
    __shared__ __align__(16) float sIn[67 * 64];
    __shared__ float sW[64 * 67];
    __shared__ float sB[64];

    int b  = blockIdx.x >> 6;
    int j0 = (blockIdx.x & 63) * 64;
    int t  = threadIdx.x;

    for (int i = t; i < 64 * 67; i += 256) sW[i] = W1[i];
    if (t < 64) sB[t] = b1[t];

    const float* fb = feat1 + (size_t)b * CF * N1;
    for (int i = t; i < 64 * 64; i += 256) {
        int c = i >> 6, j = i & 63;
        sIn[c * 64 + j] = fb[c * N1 + j0 + j];
    }
    const float* xb = xyz1 + (size_t)b * 3 * N1;
    if (t < 3 * 64) {
        int c = t >> 6, j = t & 63;
        sIn[(64 + c) * 64 + j] = xb[c * N1 + j0 + j];
    }
    __syncthreads();

    int o = t & 63, jg = t >> 6;
    float acc[16];
    float bb = sB[o];
#pragma unroll
    for (int ii = 0; ii < 16; ii++) acc[ii] = bb;

    for (int c = 0; c < 67; c++) {
        float w = sW[o * 67 + c];
        const float4* in4 = (const float4*)(sIn + c * 64 + jg * 16);
#pragma unroll
        for (int q4 = 0; q4 < 4; q4++) {
            float4 v = in4[q4];
            acc[q4 * 4 + 0] = fmaf(w, v.x, acc[q4 * 4 + 0]);
            acc[q4 * 4 + 1] = fmaf(w, v.y, acc[q4 * 4 + 1]);
            acc[q4 * 4 + 2] = fmaf(w, v.z, acc[q4 * 4 + 2]);
            acc[q4 * 4 + 3] = fmaf(w, v.w, acc[q4 * 4 + 3]);
        }
    }

    float* gp = g_gtab + ((size_t)b * N1 + j0 + jg * 16) * CF + o;
#pragma unroll
    for (int ii = 0; ii < 16; ii++) gp[ii * CF] = acc[ii];
}

// ---------------------------------------------------------------------------
// Kernel 3: top-8 KNN, one warp per query, x-sorted two-pointer window.
// Exact: every unscanned target has d^2 >= (edge dx)^2; stop when that
// exceeds the current true 8th distance. Sorted top-8 is distributed across
// lanes 0..7; inserts are warp-uniform ballot/shfl ops. Sorted positions are
// recorded during the scan; translated to original indices once at the end.
// ---------------------------------------------------------------------------
__global__ void __launch_bounds__(512) knn_kernel(const float* __restrict__ xyz2) {
    const unsigned FULL = 0xffffffffu;
    int t    = threadIdx.x;
    int lane = t & 31;
    int w    = t >> 5;               // 0..15 : query within block
    int b    = blockIdx.x >> 10;     // 1024 blocks per batch
    int q    = ((blockIdx.x & 1023) << 4) + w;

    const float* xq = xyz2 + (size_t)b * 3 * N2;
    float qx = xq[q], qy = xq[N2 + q], qz = xq[2 * N2 + q];

    const float4* P = g_spts + b * N1;
    const float*  X = g_sx   + b * N1;

    // binary search: first sorted pos with X[pos] >= qx (warp-uniform)
    int lo = 0, hi = N1;
#pragma unroll 1
    while (lo < hi) {
        int mid = (lo + hi) >> 1;
        if (X[mid] < qx) lo = mid + 1; else hi = mid;
    }
    int L = lo, R = lo;              // window [L, R) scanned

    float dk_own = 3.4e38f;          // lane r (r<8) holds list element r, ascending
    int   ik_own = 0;                // sorted position of that element
    float dk7    = 3.4e38f;

#pragma unroll 1
    while (L > 0 || R < N1) {
        float gl = (L > 0)  ? (qx - X[L - 1]) : 3.4e38f;
        float gr = (R < N1) ? (X[R] - qx)     : 3.4e38f;
        bool left = gl <= gr;
        float gap = left ? gl : gr;
        if (gap * gap > dk7) break;

        int base, cnt;
        if (left) { int nl = (L > 32) ? L - 32 : 0; base = nl; cnt = L - nl; L = nl; }
        else      { cnt = (N1 - R < 32) ? N1 - R : 32; base = R; R += cnt; }

        float d = 3.4e38f;
        if (lane < cnt) {
            float4 p = P[base + lane];
            float dx = p.x - qx, dy = p.y - qy, dz = p.z - qz;
            d = fmaf(dz, dz, fmaf(dy, dy, dx * dx));
        }
        unsigned m = __ballot_sync(FULL, d < dk7);
        while (m) {                          // warp-uniform candidate loop
            int src = __ffs(m) - 1;
            m &= m - 1;
            float dc = __shfl_sync(FULL, d, src);
            if (dc < dk7) {                  // recheck vs tightened threshold
                int jc = base + src;         // sorted position (no load here)
                unsigned gt = __ballot_sync(FULL, (lane < 8) && (dk_own > dc));
                int pos = __ffs(gt) - 1;
                float upd = __shfl_up_sync(FULL, dk_own, 1);
                int   upj = __shfl_up_sync(FULL, ik_own, 1);
                if (lane < 8) {
                    if (lane == pos)     { dk_own = dc;  ik_own = jc;  }
                    else if (lane > pos) { dk_own = upd; ik_own = upj; }
                }
                dk7 = __shfl_sync(FULL, dk_own, 7);
            }
        }
    }

    if (lane < 8)
        g_idx[((size_t)b * N2 + q) * KNN + lane] = g_sidx[b * N1 + ik_own];
}

// ---------------------------------------------------------------------------
// Kernel 4: finalize, 4 sub-threads per query (16 channels each).
// h_n = lrelu(g[idx_n] - W1_xyz @ q);  w_j[n] = W2[j].h_n  (b2 cancels);
// softmax over n; dot with flow.
// ---------------------------------------------------------------------------
__device__ __forceinline__ float softmax_dot(const float (&w)[8],
                                             const float* __restrict__ f,
                                             const int (&ik)[8]) {
    float m = w[0];
#pragma unroll
    for (int n = 1; n < 8; n++) m = fmaxf(m, w[n]);
    float s = 0.f, acc = 0.f;
#pragma unroll
    for (int n = 0; n < 8; n++) {
        float e = __expf(w[n] - m);
        s += e;
        acc = fmaf(e, __ldg(f + ik[n]), acc);
    }
    return acc / s;
}

__global__ void __launch_bounds__(256) up_kernel(const float* __restrict__ xyz2,
                                                 const float* __restrict__ flow,
                                                 const float* __restrict__ W1,
                                                 const float* __restrict__ W2,
                                                 float* __restrict__ out) {
    __shared__ float sW2[3 * 64];   // [j][o]
    __shared__ float sWx[64 * 3];   // [o][c]  (xyz columns of W1)
    int t = threadIdx.x;
    if (t < 192) sW2[t] = W2[t];
    if (t < 192) { int o = t / 3, c = t - o * 3; sWx[t] = W1[o * 67 + 64 + c]; }
    __syncthreads();

    int qL = t >> 2;          // 0..63
    int s  = t & 3;
    int b  = blockIdx.x >> 8; // 256 blocks per batch
    int q  = ((blockIdx.x & 255) << 6) + qL;

    const float* xq = xyz2 + (size_t)b * 3 * N2;
    float qx = xq[q], qy = xq[N2 + q], qz = xq[2 * N2 + q];

    const int* ip = g_idx + ((size_t)b * N2 + q) * KNN;
    int ik[8];
    {
        int4 a  = ((const int4*)ip)[0];
        int4 c4 = ((const int4*)ip)[1];
        ik[0] = a.x;  ik[1] = a.y;  ik[2] = a.z;  ik[3] = a.w;
        ik[4] = c4.x; ik[5] = c4.y; ik[6] = c4.z; ik[7] = c4.w;
    }

    const float* gb = g_gtab + (size_t)b * N1 * CF;

    float a0[8], a1[8], a2[8];
#pragma unroll
    for (int n = 0; n < 8; n++) { a0[n] = 0.f; a1[n] = 0.f; a2[n] = 0.f; }

    // sub-thread s owns o4 blocks [4s, 4s+4) = channels [16s, 16s+16)
#pragma unroll
    for (int oo = 0; oo < 4; oo++) {
        int o4 = s * 4 + oo;
        int ob = o4 * 4;
        float uu[4], wa[4], wb[4], wc[4];
#pragma unroll
        for (int i = 0; i < 4; i++) {
            int o = ob + i;
            uu[i] = fmaf(sWx[o * 3 + 2], qz, fmaf(sWx[o * 3 + 1], qy, sWx[o * 3] * qx));
            wa[i] = sW2[o];
            wb[i] = sW2[64 + o];
            wc[i] = sW2[128 + o];
        }
#pragma unroll
        for (int n = 0; n < 8; n++) {
            float4 g4 = ((const float4*)(gb + (size_t)ik[n] * CF))[o4];
            float h;
            h = g4.x - uu[0]; h = h >= 0.f ? h : 0.1f * h;
            a0[n] = fmaf(wa[0], h, a0[n]); a1[n] = fmaf(wb[0], h, a1[n]); a2[n] = fmaf(wc[0], h, a2[n]);
            h = g4.y - uu[1]; h = h >= 0.f ? h : 0.1f * h;
            a0[n] = fmaf(wa[1], h, a0[n]); a1[n] = fmaf(wb[1], h, a1[n]); a2[n] = fmaf(wc[1], h, a2[n]);
            h = g4.z - uu[2]; h = h >= 0.f ? h : 0.1f * h;
            a0[n] = fmaf(wa[2], h, a0[n]); a1[n] = fmaf(wb[2], h, a1[n]); a2[n] = fmaf(wc[2], h, a2[n]);
            h = g4.w - uu[3]; h = h >= 0.f ? h : 0.1f * h;
            a0[n] = fmaf(wa[3], h, a0[n]); a1[n] = fmaf(wb[3], h, a1[n]); a2[n] = fmaf(wc[3], h, a2[n]);
        }
    }

    // reduce the 4 sub-threads' partials (lanes 4k..4k+3 hold one query)
    const unsigned FULL = 0xffffffffu;
#pragma unroll
    for (int d = 1; d <= 2; d <<= 1) {
#pragma unroll
        for (int n = 0; n < 8; n++) {
            a0[n] += __shfl_xor_sync(FULL, a0[n], d);
            a1[n] += __shfl_xor_sync(FULL, a1[n], d);
            a2[n] += __shfl_xor_sync(FULL, a2[n], d);
        }
    }

    if (s == 0) {
        const float* fb = flow + (size_t)b * 3 * N1;
        float* ob_ = out + (size_t)b * 3 * N2;
        ob_[q]          = softmax_dot(a0, fb, ik);
        ob_[N2 + q]     = softmax_dot(a1, fb + N1, ik);
        ob_[2 * N2 + q] = softmax_dot(a2, fb + 2 * N1, ik);
    }
}

// ---------------------------------------------------------------------------
extern "C" void kernel_launch(void* const* d_in, const int* in_sizes, int n_in,
                              void* d_out, int out_size) {
    const float* xyz1  = (const float*)d_in[0];
    const float* xyz2  = (const float*)d_in[1];
    const float* feat1 = (const float*)d_in[2];
    const float* flow  = (const float*)d_in[3];
    const float* W1    = (const float*)d_in[4];
    const float* b1    = (const float*)d_in[5];
    const float* W2    = (const float*)d_in[6];
    // b2 (d_in[7]) unused: constant shift cancels in softmax over k.
    float* out = (float*)d_out;

    pack_kernel<<<(NB * N1 + 255) / 256, 256>>>(xyz1);
    sort_kernel<<<NB, 1024>>>();
    gmat_kernel<<<NB * 64, 256>>>(feat1, xyz1, W1, b1);
    knn_kernel<<<NB * 1024, 512>>>(xyz2);
    up_kernel<<<NB * 256, 256>>>(xyz2, flow, W1, W2, out);
}